// round 11
// baseline (speedup 1.0000x reference)
#include <cuda_runtime.h>
#include <stdint.h>
#include <math.h>

#define BATCH 2
#define SEQ   1024
#define DM    1024
#define NH    16
#define DK    64
#define NG    4
#define HPG   4
#define DFF   4096
#define NE    8
#define NTOK  (BATCH*SEQ)      /* 2048 */
#define NASSIGN (NTOK*2)       /* 4096 */
#define NROWS (BATCH*NH*SEQ)   /* 32768 attention rows */

/* ------------------------- scratch (device globals) ------------------------ */
__device__ float g_xr[NTOK*DM];          /* tf32-rounded */
__device__ float g_q [NTOK*DM];
__device__ float g_k [NTOK*NG*DK];
__device__ float g_v [NTOK*NG*DK];
__device__ float g_attn[NTOK*DM];        /* tf32-rounded */
__device__ float g_hn[NTOK*DM];          /* exact fp32 (router) */
__device__ float g_hnr[NTOK*DM];         /* tf32-rounded (GEMM A) */
__device__ float g_h1[(size_t)NASSIGN*DFF];  /* MoE h1; aliased as attn partial o */
__device__ float g_h2[(size_t)NASSIGN*DFF];  /* MoE h2; aliased as attn partial (m,l) */
__device__ float g_eo[NASSIGN*DM];
__device__ int   g_cnt[NE];
__device__ int   g_off[NE+1];
__device__ int   g_cur[NE];
__device__ int   g_tok[NASSIGN];
__device__ int   g_tidx[NTOK*2];
__device__ float g_twgt[NTOK*2];
__device__ int   g_trow[NTOK*2];

/* ------------------------------ helpers ----------------------------------- */

__device__ __forceinline__ uint32_t f2tf(float x){
    uint32_t r; asm("cvt.rna.tf32.f32 %0, %1;" : "=r"(r) : "f"(x)); return r;
}
__device__ __forceinline__ float f2tff(float x){
    return __uint_as_float(f2tf(x));
}
__device__ __forceinline__ void mma16n8k8(float* c, const uint32_t* a,
                                          const uint32_t* b){
    asm("mma.sync.aligned.m16n8k8.row.col.f32.tf32.tf32.f32 "
        "{%0,%1,%2,%3}, {%4,%5,%6,%7}, {%8,%9}, {%0,%1,%2,%3};"
        : "+f"(c[0]), "+f"(c[1]), "+f"(c[2]), "+f"(c[3])
        : "r"(a[0]), "r"(a[1]), "r"(a[2]), "r"(a[3]),
          "r"(b[0]), "r"(b[1]));
}
__device__ __forceinline__ void ldsm4(uint32_t* r, uint32_t addr){
    asm("ldmatrix.sync.aligned.m8n8.x4.shared.b16 {%0,%1,%2,%3}, [%4];"
        : "=r"(r[0]), "=r"(r[1]), "=r"(r[2]), "=r"(r[3]) : "r"(addr));
}
__device__ __forceinline__ float ldsf(uint32_t a){
    float v; asm("ld.shared.f32 %0, [%1];" : "=f"(v) : "r"(a)); return v;
}
__device__ __forceinline__ void cpa16(uint32_t dst, const void* src, int sz){
    asm volatile("cp.async.cg.shared.global [%0], [%1], 16, %2;"
                 :: "r"(dst), "l"(src), "r"(sz));
}
__device__ __forceinline__ void cp_commit(){
    asm volatile("cp.async.commit_group;");
}
__device__ __forceinline__ void cp_wait1(){
    asm volatile("cp.async.wait_group 1;");
}
__device__ __forceinline__ void cp_wait0(){
    asm volatile("cp.async.wait_group 0;");
}

/* ------------------------------ small kernels ------------------------------ */

__global__ void k_zero() {
    if (threadIdx.x < NE) g_cnt[threadIdx.x] = 0;
}

__global__ void k_norm_rope(const float* __restrict__ x,
                            const float* __restrict__ w) {
    int row = blockIdx.x;
    int s   = row % SEQ;
    __shared__ float xs[DM];
    __shared__ float red[256];
    const float* xp = x + (size_t)row * DM;
    float ss = 0.f;
    for (int d = threadIdx.x; d < DM; d += 256) {
        float v = xp[d]; xs[d] = v; ss += v * v;
    }
    red[threadIdx.x] = ss; __syncthreads();
    for (int st = 128; st > 0; st >>= 1) {
        if (threadIdx.x < st) red[threadIdx.x] += red[threadIdx.x + st];
        __syncthreads();
    }
    float inv = rsqrtf(red[0] / (float)DM + 1e-6f);
    float* op = g_xr + (size_t)row * DM;
    for (int k = threadIdx.x; k < DM / 2; k += 256) {
        float theta = powf(10000.f, -(float)k / (float)(DM / 2));
        float ang = (float)s * theta;
        float sn, cs; sincosf(ang, &sn, &cs);
        float xe = xs[2 * k]     * inv * w[2 * k];
        float xo = xs[2 * k + 1] * inv * w[2 * k + 1];
        op[k]          = f2tff(xe * cs - xo * sn);
        op[DM / 2 + k] = f2tff(xe * sn + xo * cs);
    }
}

/* writes exact fp32 to g_hn (router) and tf32-rounded to g_hnr (GEMM A) */
__global__ void k_rmsnorm(const float* __restrict__ src,
                          const float* __restrict__ w) {
    int row = blockIdx.x;
    __shared__ float red[256];
    const float* xp = src + (size_t)row * DM;
    float ss = 0.f;
    for (int d = threadIdx.x; d < DM; d += 256) { float v = xp[d]; ss += v * v; }
    red[threadIdx.x] = ss; __syncthreads();
    for (int st = 128; st > 0; st >>= 1) {
        if (threadIdx.x < st) red[threadIdx.x] += red[threadIdx.x + st];
        __syncthreads();
    }
    float inv = rsqrtf(red[0] / (float)DM + 1e-6f);
    float* op  = g_hn  + (size_t)row * DM;
    float* opr = g_hnr + (size_t)row * DM;
    for (int d = threadIdx.x; d < DM; d += 256) {
        float v = xp[d] * inv * w[d];
        op[d]  = v;
        opr[d] = f2tff(v);
    }
}

/* ------------- warp-MMA tf32 GEMM body, cp.async 2-stage pipeline ----------
   2 stages (70.6 KB) so 2 CTAs co-reside per SM; issue-then-wait ordering,
   double barrier per chunk keeps the 2-slot buffer race-free.
   A smem [m][k] 144B rows -> ldmatrix x4 raw; B smem [k][n] 528B rows.     */
#define A_STG    18432
#define B_STG    16896
#define STG_B    (A_STG + B_STG)       /* 35328 */
#define TG_SMEM  (2 * STG_B)           /* 70656 */

__device__ __forceinline__ void gemm_body(
        const float* __restrict__ A, int lda,
        const float* __restrict__ Bp, int Bn,
        const float* __restrict__ bi,
        const float* __restrict__ resid,
        float* __restrict__ C, int ldc,
        int rows, int row0, int mBase, int nBase, int K,
        const int* __restrict__ rowmap) {
    extern __shared__ __align__(128) char smem[];

    uint32_t sbase = (uint32_t)__cvta_generic_to_shared(smem);
    int tid = threadIdx.x, lane = tid & 31, wid = tid >> 5;
    int g = lane >> 2, t = lane & 3;
    int warp_m = wid & 1, warp_n = wid >> 1;

    const float* srcA[4]; int szA[4]; uint32_t dstA[4];
    int ac = tid & 7;
#pragma unroll
    for (int p = 0; p < 4; p++) {
        int m  = p * 32 + (tid >> 3);
        int rl = mBase + m;
        bool v = rl < rows;
        long ai = 0;
        if (v) ai = rowmap ? (long)rowmap[row0 + rl] : (long)(row0 + rl);
        srcA[p] = A + ai * (long)lda + ac * 4;
        szA[p]  = v ? 16 : 0;
        dstA[p] = (uint32_t)(m * 144 + ac * 16);
    }
    int bkr = tid >> 3;
    const float* srcB = Bp + (long)bkr * Bn + nBase + (tid & 7) * 4;
    uint32_t dstB = A_STG + (uint32_t)(bkr * 528 + (tid & 7) * 16);

    auto issue = [&](int chunk){
        uint32_t sb = sbase + (chunk & 1) * STG_B;
        long kB = (long)chunk * 32;
#pragma unroll
        for (int p = 0; p < 4; p++)
            cpa16(sb + dstA[p], srcA[p] + kB, szA[p]);
#pragma unroll
        for (int j = 0; j < 4; j++)
            cpa16(sb + dstB + j * 128, srcB + kB * Bn + j * 32, 16);
    };

    uint32_t aRowOff = (uint32_t)((warp_m * 64 + (lane & 15)) * 144
                                  + ((lane >> 4) << 4));
    uint32_t bColOff = (uint32_t)(A_STG + (warp_n * 32 + g) * 4 + t * 528);

    float acc[4][4][4];
#pragma unroll
    for (int i = 0; i < 4; i++)
#pragma unroll
        for (int j = 0; j < 4; j++)
#pragma unroll
            for (int q = 0; q < 4; q++) acc[i][j][q] = 0.f;

    int nCh = K >> 5;

    issue(0);
    cp_commit();

    for (int kc = 0; kc < nCh; kc++) {
        if (kc + 1 < nCh) {
            issue(kc + 1);
            cp_commit();
            cp_wait1();            /* chunk kc arrived */
        } else {
            cp_wait0();
        }
        __syncthreads();           /* chunk kc visible to all */

        uint32_t sb = sbase + (kc & 1) * STG_B;
#pragma unroll
        for (int ks = 0; ks < 4; ks++) {
            uint32_t ar[4][4], br[4][2];
#pragma unroll
            for (int mt = 0; mt < 4; mt++)
                ldsm4(ar[mt], sb + aRowOff + mt * 2304 + ks * 32);
            uint32_t ba = sb + bColOff + ks * (8 * 528);
#pragma unroll
            for (int nt = 0; nt < 4; nt++) {
                br[nt][0] = f2tf(ldsf(ba + nt * 32));
                br[nt][1] = f2tf(ldsf(ba + nt * 32 + 4 * 528));
            }
#pragma unroll
            for (int mt = 0; mt < 4; mt++)
#pragma unroll
                for (int nt = 0; nt < 4; nt++)
                    mma16n8k8(acc[mt][nt], ar[mt], br[nt]);
        }
        __syncthreads();           /* done reading slot before it is refilled */
    }

#pragma unroll
    for (int mt = 0; mt < 4; mt++) {
        int rl0 = mBase + warp_m * 64 + mt * 16 + g;
#pragma unroll
        for (int half = 0; half < 2; half++) {
            int rl = rl0 + half * 8;
            if (rl >= rows) continue;
            long cRow = row0 + rl;
            float* Crow = C + cRow * (long)ldc;
            const float* Rrow = resid ? (resid + cRow * (long)ldc) : (const float*)0;
#pragma unroll
            for (int nt = 0; nt < 4; nt++) {
                int c = nBase + warp_n * 32 + nt * 8 + 2 * t;
                float v0 = acc[mt][nt][half * 2 + 0];
                float v1 = acc[mt][nt][half * 2 + 1];
                if (bi)   { v0 += bi[c];   v1 += bi[c + 1]; }
                if (Rrow) { v0 += Rrow[c]; v1 += Rrow[c + 1]; }
                *(float2*)(Crow + c) = make_float2(v0, v1);
            }
        }
    }
}

__global__ void __launch_bounds__(256, 2)
k_tgemm(const float* __restrict__ A, int lda,
        const float* __restrict__ Bmat, long bstride,
        const float* __restrict__ bias, long biasStride,
        const float* __restrict__ resid,
        float* __restrict__ C, int ldc,
        int M, int N, int K,
        const int* __restrict__ segoff,
        const int* __restrict__ rowmap) {
    int e = blockIdx.z;
    int row0 = 0, rows = M;
    if (segoff) { row0 = segoff[e]; rows = segoff[e + 1] - row0; }
    int mBase = blockIdx.y * 128;
    if (mBase >= rows) return;
    gemm_body(A, lda,
              Bmat + (long)e * bstride, N,
              bias ? (bias + (long)e * biasStride) : (const float*)0,
              resid, C, ldc,
              rows, row0, mBase, blockIdx.x * 128, K, rowmap);
}

/* fused Q/K/V projection: grid (12, 16); x<8 -> Q, 8..9 -> K, 10..11 -> V */
__global__ void __launch_bounds__(256, 2)
k_qkv(const float* __restrict__ Wq, const float* __restrict__ Wk,
      const float* __restrict__ Wv) {
    int x = blockIdx.x;
    const float* B; float* C; int Bn, col0;
    if (x < 8)       { B = Wq; C = g_q; Bn = DM;      col0 = x * 128; }
    else if (x < 10) { B = Wk; C = g_k; Bn = NG * DK; col0 = (x - 8) * 128; }
    else             { B = Wv; C = g_v; Bn = NG * DK; col0 = (x - 10) * 128; }
    gemm_body(g_xr, DM, B, Bn, 0, 0, C, Bn,
              NTOK, 0, blockIdx.y * 128, col0, DM, 0);
}

/* ----------------- split-K flash attention (partials) ----------------------
   blockIdx.x enumerates (qt, kc) pairs: qt in 0..7, kc in 0..qt  (36 total).
   Each CTA: 128 query rows, 128 keys, partial m/l/o.  float4 smem loads.
   Partials: o -> g_h1 [(kc*64+d)*NROWS + r], (m,l) -> g_h2 float2[r*8+kc]. */
__global__ void __launch_bounds__(128)
k_attn_split() {
    int fx = blockIdx.x;
    int qt = 0;
#pragma unroll
    for (int q = 1; q < 8; q++) if (fx >= (q * (q + 1)) / 2) qt = q;
    int kc = fx - (qt * (qt + 1)) / 2;
    int h  = blockIdx.y;
    int b  = blockIdx.z;
    int g  = h / HPG;
    int tid = threadIdx.x;
    int i  = qt * 128 + tid;
    bool diag = (kc == qt);

    __shared__ float Ks[64][DK];
    __shared__ float Vs[64][DK];

    float q[DK];
    const float* qp = g_q + ((size_t)(b * SEQ + i)) * DM + h * DK;
#pragma unroll
    for (int d = 0; d < DK; d++) q[d] = qp[d] * 0.125f;

    float o[DK];
#pragma unroll
    for (int d = 0; d < DK; d++) o[d] = 0.f;
    float m = -1e30f, l = 0.f;

    for (int kt = 0; kt < 2; kt++) {
        int j0 = kc * 128 + kt * 64;
        __syncthreads();
        for (int tt = tid; tt < 64 * (DK / 4); tt += 128) {
            int jj = tt / (DK / 4), d4 = tt % (DK / 4);
            size_t src = ((size_t)(b * SEQ + j0 + jj)) * (NG * DK) + g * DK + d4 * 4;
            *(float4*)&Ks[jj][d4 * 4] = *(const float4*)&g_k[src];
            *(float4*)&Vs[jj][d4 * 4] = *(const float4*)&g_v[src];
        }
        __syncthreads();

        for (int c0 = 0; c0 < 64; c0 += 32) {
            float s[32];
            for (int jj = 0; jj < 32; jj++) {
                const float4* kp = (const float4*)&Ks[c0 + jj][0];
                float acc = 0.f;
#pragma unroll
                for (int d4 = 0; d4 < DK / 4; d4++) {
                    float4 kv = kp[d4];
                    acc += q[4*d4+0] * kv.x + q[4*d4+1] * kv.y
                         + q[4*d4+2] * kv.z + q[4*d4+3] * kv.w;
                }
                bool ok = !diag || (j0 + c0 + jj <= i);
                s[jj] = ok ? acc : -1e30f;
            }
            float mn = m;
            for (int jj = 0; jj < 32; jj++) mn = fmaxf(mn, s[jj]);
            float scale = __expf(m - mn);
            m = mn;
            l *= scale;
#pragma unroll
            for (int d = 0; d < DK; d++) o[d] *= scale;
            for (int jj = 0; jj < 32; jj++) {
                bool ok = !diag || (j0 + c0 + jj <= i);
                float p = ok ? __expf(s[jj] - mn) : 0.f;
                l += p;
                const float4* vp = (const float4*)&Vs[c0 + jj][0];
#pragma unroll
                for (int d4 = 0; d4 < DK / 4; d4++) {
                    float4 vv = vp[d4];
                    o[4*d4+0] += p * vv.x; o[4*d4+1] += p * vv.y;
                    o[4*d4+2] += p * vv.z; o[4*d4+3] += p * vv.w;
                }
            }
        }
    }

    int r = ((b * NH + h) << 10) + i;     /* SEQ = 1024 */
    float* po = g_h1;
#pragma unroll
    for (int d = 0; d < DK; d++)
        po[((size_t)(kc * DK + d)) * NROWS + r] = o[d];
    ((float2*)g_h2)[r * 8 + kc] = make_float2(m, l);
}

/* combine partials -> g_attn (tf32-rounded). One thread per row. */
__global__ void __launch_bounds__(256)
k_attn_combine() {
    int r = blockIdx.x * 256 + threadIdx.x;   /* 0..NROWS-1 */
    int s  = r & (SEQ - 1);
    int hb = r >> 10;
    int h  = hb & (NH - 1);
    int b  = hb >> 4;
    int nch = (s >> 7) + 1;

    const float*  po = g_h1;
    const float2* ml = (const float2*)g_h2;

    float2 mlc[8];
    float M = -1e30f;
    for (int c = 0; c < nch; c++) {
        mlc[c] = ml[r * 8 + c];
        M = fmaxf(M, mlc[c].x);
    }
    float w[8];
    float l = 0.f;
    for (int c = 0; c < nch; c++) {
        w[c] = __expf(mlc[c].x - M);
        l += w[c] * mlc[c].y;
    }
    float invl = 1.f / l;

    float* op = g_attn + ((size_t)(b * SEQ + s)) * DM + h * DK;
#pragma unroll
    for (int d = 0; d < DK; d++) {
        float acc = 0.f;
        for (int c = 0; c < nch; c++)
            acc += w[c] * po[((size_t)(c * DK + d)) * NROWS + r];
        op[d] = f2tff(acc * invl);
    }
}

/* ------------------------------- MoE routing ------------------------------ */

__global__ void k_router(const float* __restrict__ rw,
                         const float* __restrict__ rb) {
    int t    = blockIdx.x * 8 + (threadIdx.x >> 5);
    int lane = threadIdx.x & 31;
    float part[NE];
#pragma unroll
    for (int e = 0; e < NE; e++) part[e] = 0.f;
    const float* hp = g_hn + (size_t)t * DM;
    for (int d = lane; d < DM; d += 32) {
        float hv = hp[d];
        const float* rp = rw + (size_t)d * NE;
#pragma unroll
        for (int e = 0; e < NE; e++) part[e] += hv * rp[e];
    }
#pragma unroll
    for (int e = 0; e < NE; e++)
        for (int off = 16; off > 0; off >>= 1)
            part[e] += __shfl_xor_sync(0xffffffffu, part[e], off);
    if (lane == 0) {
        float lg[NE];
#pragma unroll
        for (int e = 0; e < NE; e++) lg[e] = part[e] + rb[e];
        int i0 = 0;
        for (int e = 1; e < NE; e++) if (lg[e] > lg[i0]) i0 = e;
        int i1 = (i0 == 0) ? 1 : 0;
        for (int e = 0; e < NE; e++)
            if (e != i0 && lg[e] > lg[i1]) i1 = e;
        float e1 = __expf(lg[i1] - lg[i0]);
        float inv = 1.f / (1.f + e1);
        g_tidx[t * 2 + 0] = i0; g_tidx[t * 2 + 1] = i1;
        g_twgt[t * 2 + 0] = inv; g_twgt[t * 2 + 1] = e1 * inv;
        atomicAdd(&g_cnt[i0], 1);
        atomicAdd(&g_cnt[i1], 1);
    }
}

__global__ void k_scan() {
    if (threadIdx.x == 0) {
        int acc = 0;
        for (int e = 0; e < NE; e++) {
            g_off[e] = acc; acc += g_cnt[e]; g_cur[e] = 0;
        }
        g_off[NE] = acc;
    }
}

__global__ void k_scatter() {
    int t = blockIdx.x * 256 + threadIdx.x;
    if (t >= NTOK) return;
#pragma unroll
    for (int k = 0; k < 2; k++) {
        int e = g_tidx[t * 2 + k];
        int p = atomicAdd(&g_cur[e], 1);
        int row = g_off[e] + p;
        g_tok[row] = t;
        g_trow[t * 2 + k] = row;
    }
}

__global__ void k_silu() {
    size_t i = ((size_t)blockIdx.x * 256 + threadIdx.x) * 4;
    float4 a = *(float4*)&g_h1[i];
    float4 b = *(float4*)&g_h2[i];
    a.x = f2tff(b.x * a.x / (1.f + __expf(-a.x)));
    a.y = f2tff(b.y * a.y / (1.f + __expf(-a.y)));
    a.z = f2tff(b.z * a.z / (1.f + __expf(-a.z)));
    a.w = f2tff(b.w * a.w / (1.f + __expf(-a.w)));
    *(float4*)&g_h1[i] = a;
}

__global__ void k_combine(float* __restrict__ out) {
    int t = blockIdx.x;
    int   r0 = g_trow[t * 2],     r1 = g_trow[t * 2 + 1];
    float w0 = g_twgt[t * 2],     w1 = g_twgt[t * 2 + 1];
    const float* e0 = g_eo + (size_t)r0 * DM;
    const float* e1 = g_eo + (size_t)r1 * DM;
    float* op = out + (size_t)t * DM;
    for (int d = threadIdx.x; d < DM; d += 256)
        op[d] += w0 * e0[d] + w1 * e1[d];
}

/* --------------------------------- driver --------------------------------- */

extern "C" void kernel_launch(void* const* d_in, const int* in_sizes, int n_in,
                              void* d_out, int out_size) {
    const float* x   = (const float*)d_in[0];
    const float* n1w = (const float*)d_in[1];
    const float* Wq  = (const float*)d_in[2];
    const float* Wk  = (const float*)d_in[3];
    const float* Wv  = (const float*)d_in[4];
    const float* Wo  = (const float*)d_in[5];
    const float* n2w = (const float*)d_in[6];
    const float* rw  = (const float*)d_in[7];
    const float* rb  = (const float*)d_in[8];
    const float* W1  = (const float*)d_in[9];
    const float* b1  = (const float*)d_in[10];
    const float* W2  = (const float*)d_in[11];
    const float* b2  = (const float*)d_in[12];
    const float* W3  = (const float*)d_in[13];
    const float* b3  = (const float*)d_in[14];
    float* out = (float*)d_out;

    cudaFuncSetAttribute(k_tgemm, cudaFuncAttributeMaxDynamicSharedMemorySize,
                         TG_SMEM);
    cudaFuncSetAttribute(k_qkv, cudaFuncAttributeMaxDynamicSharedMemorySize,
                         TG_SMEM);

    void *p_attn, *p_hnr, *p_h1, *p_h2, *p_eo, *p_off, *p_tok;
    cudaGetSymbolAddress(&p_attn, g_attn);
    cudaGetSymbolAddress(&p_hnr,  g_hnr);
    cudaGetSymbolAddress(&p_h1,   g_h1);
    cudaGetSymbolAddress(&p_h2,   g_h2);
    cudaGetSymbolAddress(&p_eo,   g_eo);
    cudaGetSymbolAddress(&p_off,  g_off);
    cudaGetSymbolAddress(&p_tok,  g_tok);
    float* attn = (float*)p_attn;
    float* hnr  = (float*)p_hnr;
    float* h1b  = (float*)p_h1;
    float* h2b  = (float*)p_h2;
    float* eob  = (float*)p_eo;
    int*   offp = (int*)p_off;
    int*   tokp = (int*)p_tok;

    k_zero<<<1, 32>>>();
    k_norm_rope<<<NTOK, 256>>>(x, n1w);

    /* fused Q/K/V projections */
    k_qkv<<<dim3(12, NTOK/128, 1), 256, TG_SMEM>>>(Wq, Wk, Wv);

    /* split-K flash attention: partials, then combine */
    k_attn_split<<<dim3(36, NH, BATCH), 128>>>();
    k_attn_combine<<<NROWS/256, 256>>>();

    /* out = x + attn @ Wo */
    k_tgemm<<<dim3(DM/128, NTOK/128, 1), 256, TG_SMEM>>>(
        attn, DM, Wo, 0, 0, 0, x, out, DM, NTOK, DM, DM, 0, 0);

    k_rmsnorm<<<NTOK, 256>>>(out, n2w);

    k_router<<<NTOK/8, 256>>>(rw, rb);
    k_scan<<<1, 32>>>();
    k_scatter<<<NTOK/256, 256>>>();

    /* expert FFN */
    k_tgemm<<<dim3(DFF/128, NTOK/128, NE), 256, TG_SMEM>>>(
        hnr, DM, W1, (long)DM*DFF, b1, DFF, 0,
        h1b, DFF, 0, DFF, DM, offp, tokp);
    k_tgemm<<<dim3(DFF/128, NTOK/128, NE), 256, TG_SMEM>>>(
        hnr, DM, W2, (long)DM*DFF, b2, DFF, 0,
        h2b, DFF, 0, DFF, DM, offp, tokp);
    k_silu<<<(NASSIGN*(DFF/4))/256, 256>>>();
    k_tgemm<<<dim3(DM/128, NTOK/128, NE), 256, TG_SMEM>>>(
        h1b, DFF, W3, (long)DFF*DM, b3, DM, 0,
        eob, DM, 0, DM, DFF, offp, 0);

    k_combine<<<NTOK, 256>>>(out);
}

// round 13
// speedup vs baseline: 1.2199x; 1.2199x over previous
#include <cuda_runtime.h>
#include <cuda_fp16.h>
#include <stdint.h>
#include <math.h>

#define BATCH 2
#define SEQ   1024
#define DM    1024
#define NH    16
#define DK    64
#define NG    4
#define HPG   4
#define DFF   4096
#define NE    8
#define NTOK  (BATCH*SEQ)      /* 2048 */
#define NASSIGN (NTOK*2)       /* 4096 */
#define NROWS (BATCH*NH*SEQ)   /* 32768 attention rows */

/* ------------------------- scratch (device globals) ------------------------ */
__device__ float  g_q [NTOK*DM];
__device__ float  g_k [NTOK*NG*DK];
__device__ float  g_v [NTOK*NG*DK];
__device__ float  g_hn[NTOK*DM];             /* exact fp32 (router) */
__device__ float  g_h1[(size_t)NASSIGN*DFF]; /* MoE h1; alias attn partial o */
__device__ float  g_h2[(size_t)NASSIGN*DFF]; /* MoE h2; alias attn (m,l) */
__device__ float  g_eo[NASSIGN*DM];
__device__ __half g_xrh [NTOK*DM];           /* rmsnorm1+rope (GEMM A) */
__device__ __half g_attnh[NTOK*DM];          /* attention out (GEMM A) */
__device__ __half g_hnrh[NTOK*DM];           /* rmsnorm2 (GEMM A) */
__device__ __half g_hh[(size_t)NASSIGN*DFF]; /* silu out (GEMM A) */
__device__ __half g_wq[DM*DM];
__device__ __half g_wk[DM*NG*DK];
__device__ __half g_wv[DM*NG*DK];
__device__ __half g_wo[DM*DM];
__device__ __half g_w1[(size_t)NE*DM*DFF];
__device__ __half g_w2[(size_t)NE*DM*DFF];
__device__ __half g_w3[(size_t)NE*DFF*DM];
__device__ int    g_cnt[NE];
__device__ int    g_off[NE+1];
__device__ int    g_cur[NE];
__device__ int    g_tok[NASSIGN];
__device__ int    g_tidx[NTOK*2];
__device__ float  g_twgt[NTOK*2];
__device__ int    g_trow[NTOK*2];

/* ------------------------------ helpers ----------------------------------- */

__device__ __forceinline__ void mmaf16(float* c, const uint32_t* a,
                                       const uint32_t* b){
    asm("mma.sync.aligned.m16n8k16.row.col.f32.f16.f16.f32 "
        "{%0,%1,%2,%3}, {%4,%5,%6,%7}, {%8,%9}, {%0,%1,%2,%3};"
        : "+f"(c[0]), "+f"(c[1]), "+f"(c[2]), "+f"(c[3])
        : "r"(a[0]), "r"(a[1]), "r"(a[2]), "r"(a[3]),
          "r"(b[0]), "r"(b[1]));
}
__device__ __forceinline__ void ldsm4(uint32_t* r, uint32_t addr){
    asm("ldmatrix.sync.aligned.m8n8.x4.shared.b16 {%0,%1,%2,%3}, [%4];"
        : "=r"(r[0]), "=r"(r[1]), "=r"(r[2]), "=r"(r[3]) : "r"(addr));
}
__device__ __forceinline__ void ldsm4t(uint32_t* r, uint32_t addr){
    asm("ldmatrix.sync.aligned.m8n8.x4.trans.shared.b16 {%0,%1,%2,%3}, [%4];"
        : "=r"(r[0]), "=r"(r[1]), "=r"(r[2]), "=r"(r[3]) : "r"(addr));
}
__device__ __forceinline__ void cpa16(uint32_t dst, const void* src, int sz){
    asm volatile("cp.async.cg.shared.global [%0], [%1], 16, %2;"
                 :: "r"(dst), "l"(src), "r"(sz));
}
__device__ __forceinline__ void cp_commit(){
    asm volatile("cp.async.commit_group;");
}
__device__ __forceinline__ void cp_wait1(){
    asm volatile("cp.async.wait_group 1;");
}

/* ------------------------------ small kernels ------------------------------ */

__global__ void k_zero() {
    if (threadIdx.x < NE) g_cnt[threadIdx.x] = 0;
}

/* weight fp32 -> fp16 conversion */
__global__ void k_cvt(const float4* __restrict__ src,
                      __half2* __restrict__ dst, int n4) {
    int i = blockIdx.x * 256 + threadIdx.x;
    if (i >= n4) return;
    float4 v = src[i];
    dst[2*i]   = __floats2half2_rn(v.x, v.y);
    dst[2*i+1] = __floats2half2_rn(v.z, v.w);
}

__global__ void k_norm_rope(const float* __restrict__ x,
                            const float* __restrict__ w) {
    int row = blockIdx.x;
    int s   = row % SEQ;
    __shared__ float xs[DM];
    __shared__ float red[256];
    const float* xp = x + (size_t)row * DM;
    float ss = 0.f;
    for (int d = threadIdx.x; d < DM; d += 256) {
        float v = xp[d]; xs[d] = v; ss += v * v;
    }
    red[threadIdx.x] = ss; __syncthreads();
    for (int st = 128; st > 0; st >>= 1) {
        if (threadIdx.x < st) red[threadIdx.x] += red[threadIdx.x + st];
        __syncthreads();
    }
    float inv = rsqrtf(red[0] / (float)DM + 1e-6f);
    __half* op = g_xrh + (size_t)row * DM;
    for (int k = threadIdx.x; k < DM / 2; k += 256) {
        float theta = powf(10000.f, -(float)k / (float)(DM / 2));
        float ang = (float)s * theta;
        float sn, cs; sincosf(ang, &sn, &cs);
        float xe = xs[2 * k]     * inv * w[2 * k];
        float xo = xs[2 * k + 1] * inv * w[2 * k + 1];
        op[k]          = __float2half(xe * cs - xo * sn);
        op[DM / 2 + k] = __float2half(xe * sn + xo * cs);
    }
}

/* exact fp32 -> g_hn (router), fp16 -> g_hnrh (GEMM A) */
__global__ void k_rmsnorm(const float* __restrict__ src,
                          const float* __restrict__ w) {
    int row = blockIdx.x;
    __shared__ float red[256];
    const float* xp = src + (size_t)row * DM;
    float ss = 0.f;
    for (int d = threadIdx.x; d < DM; d += 256) { float v = xp[d]; ss += v * v; }
    red[threadIdx.x] = ss; __syncthreads();
    for (int st = 128; st > 0; st >>= 1) {
        if (threadIdx.x < st) red[threadIdx.x] += red[threadIdx.x + st];
        __syncthreads();
    }
    float inv = rsqrtf(red[0] / (float)DM + 1e-6f);
    float*  op  = g_hn   + (size_t)row * DM;
    __half* opr = g_hnrh + (size_t)row * DM;
    for (int d = threadIdx.x; d < DM; d += 256) {
        float v = xp[d] * inv * w[d];
        op[d]  = v;
        opr[d] = __float2half(v);
    }
}

/* ----------------- fp16 warp-MMA GEMM, cp.async 3-stage --------------------
   BM=128 BN=128 BK=32, 512 thr, 16 warps (4m x 4n), warp tile 32x32.
   A smem [m][k] fp16 rows 64B pad->80B : ldmatrix x4 fragments.
   B smem [k][n] fp16 rows 256B pad->272B : ldmatrix x4 TRANS fragments.
   Zero conversions in the loop; weights pre-converted to fp16.             */
#define A_STG    10240                 /* 128 * 80 */
#define B_STG    8704                  /* 32 * 272 */
#define STG_B    (A_STG + B_STG)       /* 18944 */
#define TG_SMEM  (3 * STG_B)           /* 56832 */

__device__ __forceinline__ void gemm_body(
        const __half* __restrict__ A, int lda,
        const __half* __restrict__ Bp, int Bn,
        const float* __restrict__ bi,
        const float* __restrict__ resid,
        float* __restrict__ C, int ldc,
        int rows, int row0, int mBase, int nBase, int K,
        const int* __restrict__ rowmap) {
    extern __shared__ __align__(128) char smem[];

    uint32_t sbase = (uint32_t)__cvta_generic_to_shared(smem);
    int tid = threadIdx.x, lane = tid & 31, wid = tid >> 5;
    int g = lane >> 2, t = lane & 3;
    int warp_m = wid & 3, warp_n = wid >> 2;

    /* A copy: row = tid>>2 (0..127), 16B chunk = tid&3 */
    int amr = tid >> 2;
    bool av = (mBase + amr) < rows;
    long ai = 0;
    if (av) ai = rowmap ? (long)rowmap[row0 + mBase + amr]
                        : (long)(row0 + mBase + amr);
    const __half* srcA = A + ai * (long)lda + (tid & 3) * 8;
    uint32_t dstA = (uint32_t)(amr * 80 + (tid & 3) * 16);
    int szA = av ? 16 : 0;

    /* B copy: k-row = tid>>4 (0..31), 16B chunk = tid&15 */
    int bkr = tid >> 4;
    const __half* srcB = Bp + (long)bkr * Bn + nBase + (tid & 15) * 8;
    uint32_t dstB = (uint32_t)(A_STG + bkr * 272 + (tid & 15) * 16);

    auto issue = [&](int c){
        uint32_t sb = sbase + (c % 3) * STG_B;
        cpa16(sb + dstA, srcA + (long)c * 32, szA);
        cpa16(sb + dstB, srcB + (long)c * 32 * Bn, 16);
    };

    /* fragment bases */
    uint32_t aOff  = (uint32_t)((warp_m * 32 + (lane & 15)) * 80
                                + (lane >> 4) * 16);
    uint32_t bBase = (uint32_t)(A_STG
                     + ((lane & 7) + ((lane >> 3) & 1) * 8) * 272
                     + (warp_n * 32 + (lane >> 4) * 8) * 2);

    float acc[2][4][4];
#pragma unroll
    for (int i = 0; i < 2; i++)
#pragma unroll
        for (int j = 0; j < 4; j++)
#pragma unroll
            for (int q = 0; q < 4; q++) acc[i][j][q] = 0.f;

    int nCh = K >> 5;

    issue(0); cp_commit();
    if (nCh > 1) issue(1);
    cp_commit();

    for (int kc = 0; kc < nCh; kc++) {
        cp_wait1();                /* chunk kc resident */
        __syncthreads();

        int nk = kc + 2;
        if (nk < nCh) issue(nk);
        cp_commit();

        uint32_t sb = sbase + (kc % 3) * STG_B;
#pragma unroll
        for (int ks = 0; ks < 2; ks++) {
            uint32_t ar[2][4], br[4][2];
#pragma unroll
            for (int mt = 0; mt < 2; mt++)
                ldsm4(ar[mt], sb + aOff + mt * 1280 + ks * 32);
#pragma unroll
            for (int ng = 0; ng < 2; ng++) {
                uint32_t r[4];
                ldsm4t(r, sb + bBase + ks * 4352 + ng * 32);
                br[ng*2+0][0] = r[0]; br[ng*2+0][1] = r[1];
                br[ng*2+1][0] = r[2]; br[ng*2+1][1] = r[3];
            }
#pragma unroll
            for (int mt = 0; mt < 2; mt++)
#pragma unroll
                for (int nt = 0; nt < 4; nt++)
                    mmaf16(acc[mt][nt], ar[mt], br[nt]);
        }
    }

    /* epilogue */
#pragma unroll
    for (int mt = 0; mt < 2; mt++) {
        int rl0 = mBase + warp_m * 32 + mt * 16 + g;
#pragma unroll
        for (int half = 0; half < 2; half++) {
            int rl = rl0 + half * 8;
            if (rl >= rows) continue;
            long cRow = row0 + rl;
            float* Crow = C + cRow * (long)ldc;
            const float* Rrow = resid ? (resid + cRow * (long)ldc) : (const float*)0;
#pragma unroll
            for (int nt = 0; nt < 4; nt++) {
                int c = nBase + warp_n * 32 + nt * 8 + 2 * t;
                float v0 = acc[mt][nt][half * 2 + 0];
                float v1 = acc[mt][nt][half * 2 + 1];
                if (bi)   { v0 += bi[c];   v1 += bi[c + 1]; }
                if (Rrow) { v0 += Rrow[c]; v1 += Rrow[c + 1]; }
                *(float2*)(Crow + c) = make_float2(v0, v1);
            }
        }
    }
}

__global__ void __launch_bounds__(512, 1)
k_tgemm(const __half* __restrict__ A, int lda,
        const __half* __restrict__ Bmat, long bstride,
        const float* __restrict__ bias, long biasStride,
        const float* __restrict__ resid,
        float* __restrict__ C, int ldc,
        int M, int N, int K,
        const int* __restrict__ segoff,
        const int* __restrict__ rowmap) {
    int e = blockIdx.z;
    int row0 = 0, rows = M;
    if (segoff) { row0 = segoff[e]; rows = segoff[e + 1] - row0; }
    int mBase = blockIdx.y * 128;
    if (mBase >= rows) return;
    gemm_body(A, lda,
              Bmat + (long)e * bstride, N,
              bias ? (bias + (long)e * biasStride) : (const float*)0,
              resid, C, ldc,
              rows, row0, mBase, blockIdx.x * 128, K, rowmap);
}

/* fused Q/K/V projection: grid (12, 16); x<8 -> Q, 8..9 -> K, 10..11 -> V */
__global__ void __launch_bounds__(512, 1)
k_qkv() {
    int x = blockIdx.x;
    const __half* B; float* C; int Bn, col0;
    if (x < 8)       { B = g_wq; C = g_q; Bn = DM;      col0 = x * 128; }
    else if (x < 10) { B = g_wk; C = g_k; Bn = NG * DK; col0 = (x - 8) * 128; }
    else             { B = g_wv; C = g_v; Bn = NG * DK; col0 = (x - 10) * 128; }
    gemm_body(g_xrh, DM, B, Bn, 0, 0, C, Bn,
              NTOK, 0, blockIdx.y * 128, col0, DM, 0);
}

/* ----------------- split-K flash attention (partials) ---------------------- */
__global__ void __launch_bounds__(128)
k_attn_split() {
    int fx = blockIdx.x;
    int qt = 0;
#pragma unroll
    for (int q = 1; q < 8; q++) if (fx >= (q * (q + 1)) / 2) qt = q;
    int kc = fx - (qt * (qt + 1)) / 2;
    int h  = blockIdx.y;
    int b  = blockIdx.z;
    int g  = h / HPG;
    int tid = threadIdx.x;
    int i  = qt * 128 + tid;
    bool diag = (kc == qt);

    __shared__ float Ks[64][DK];
    __shared__ float Vs[64][DK];

    float q[DK];
    const float* qp = g_q + ((size_t)(b * SEQ + i)) * DM + h * DK;
#pragma unroll
    for (int d = 0; d < DK; d++) q[d] = qp[d] * 0.125f;

    float o[DK];
#pragma unroll
    for (int d = 0; d < DK; d++) o[d] = 0.f;
    float m = -1e30f, l = 0.f;

    for (int kt = 0; kt < 2; kt++) {
        int j0 = kc * 128 + kt * 64;
        __syncthreads();
        for (int tt = tid; tt < 64 * (DK / 4); tt += 128) {
            int jj = tt / (DK / 4), d4 = tt % (DK / 4);
            size_t src = ((size_t)(b * SEQ + j0 + jj)) * (NG * DK) + g * DK + d4 * 4;
            *(float4*)&Ks[jj][d4 * 4] = *(const float4*)&g_k[src];
            *(float4*)&Vs[jj][d4 * 4] = *(const float4*)&g_v[src];
        }
        __syncthreads();

        for (int c0 = 0; c0 < 64; c0 += 32) {
            float s[32];
            for (int jj = 0; jj < 32; jj++) {
                const float4* kp = (const float4*)&Ks[c0 + jj][0];
                float acc = 0.f;
#pragma unroll
                for (int d4 = 0; d4 < DK / 4; d4++) {
                    float4 kv = kp[d4];
                    acc += q[4*d4+0] * kv.x + q[4*d4+1] * kv.y
                         + q[4*d4+2] * kv.z + q[4*d4+3] * kv.w;
                }
                bool ok = !diag || (j0 + c0 + jj <= i);
                s[jj] = ok ? acc : -1e30f;
            }
            float mn = m;
            for (int jj = 0; jj < 32; jj++) mn = fmaxf(mn, s[jj]);
            float scale = __expf(m - mn);
            m = mn;
            l *= scale;
#pragma unroll
            for (int d = 0; d < DK; d++) o[d] *= scale;
            for (int jj = 0; jj < 32; jj++) {
                bool ok = !diag || (j0 + c0 + jj <= i);
                float p = ok ? __expf(s[jj] - mn) : 0.f;
                l += p;
                const float4* vp = (const float4*)&Vs[c0 + jj][0];
#pragma unroll
                for (int d4 = 0; d4 < DK / 4; d4++) {
                    float4 vv = vp[d4];
                    o[4*d4+0] += p * vv.x; o[4*d4+1] += p * vv.y;
                    o[4*d4+2] += p * vv.z; o[4*d4+3] += p * vv.w;
                }
            }
        }
    }

    int r = ((b * NH + h) << 10) + i;     /* SEQ = 1024 */
    float* po = g_h1;
#pragma unroll
    for (int d = 0; d < DK; d++)
        po[((size_t)(kc * DK + d)) * NROWS + r] = o[d];
    ((float2*)g_h2)[r * 8 + kc] = make_float2(m, l);
}

/* combine partials -> g_attnh (fp16). One thread per row. */
__global__ void __launch_bounds__(256)
k_attn_combine() {
    int r = blockIdx.x * 256 + threadIdx.x;   /* 0..NROWS-1 */
    int s  = r & (SEQ - 1);
    int hb = r >> 10;
    int h  = hb & (NH - 1);
    int b  = hb >> 4;
    int nch = (s >> 7) + 1;

    const float*  po = g_h1;
    const float2* ml = (const float2*)g_h2;

    float2 mlc[8];
    float M = -1e30f;
    for (int c = 0; c < nch; c++) {
        mlc[c] = ml[r * 8 + c];
        M = fmaxf(M, mlc[c].x);
    }
    float w[8];
    float l = 0.f;
    for (int c = 0; c < nch; c++) {
        w[c] = __expf(mlc[c].x - M);
        l += w[c] * mlc[c].y;
    }
    float invl = 1.f / l;

    __half* op = g_attnh + ((size_t)(b * SEQ + s)) * DM + h * DK;
#pragma unroll
    for (int d = 0; d < DK; d++) {
        float acc = 0.f;
        for (int c = 0; c < nch; c++)
            acc += w[c] * po[((size_t)(c * DK + d)) * NROWS + r];
        op[d] = __float2half(acc * invl);
    }
}

/* ------------------------------- MoE routing ------------------------------ */

__global__ void k_router(const float* __restrict__ rw,
                         const float* __restrict__ rb) {
    int t    = blockIdx.x * 8 + (threadIdx.x >> 5);
    int lane = threadIdx.x & 31;
    float part[NE];
#pragma unroll
    for (int e = 0; e < NE; e++) part[e] = 0.f;
    const float* hp = g_hn + (size_t)t * DM;
    for (int d = lane; d < DM; d += 32) {
        float hv = hp[d];
        const float* rp = rw + (size_t)d * NE;
#pragma unroll
        for (int e = 0; e < NE; e++) part[e] += hv * rp[e];
    }
#pragma unroll
    for (int e = 0; e < NE; e++)
        for (int off = 16; off > 0; off >>= 1)
            part[e] += __shfl_xor_sync(0xffffffffu, part[e], off);
    if (lane == 0) {
        float lg[NE];
#pragma unroll
        for (int e = 0; e < NE; e++) lg[e] = part[e] + rb[e];
        int i0 = 0;
        for (int e = 1; e < NE; e++) if (lg[e] > lg[i0]) i0 = e;
        int i1 = (i0 == 0) ? 1 : 0;
        for (int e = 0; e < NE; e++)
            if (e != i0 && lg[e] > lg[i1]) i1 = e;
        float e1 = __expf(lg[i1] - lg[i0]);
        float inv = 1.f / (1.f + e1);
        g_tidx[t * 2 + 0] = i0; g_tidx[t * 2 + 1] = i1;
        g_twgt[t * 2 + 0] = inv; g_twgt[t * 2 + 1] = e1 * inv;
        atomicAdd(&g_cnt[i0], 1);
        atomicAdd(&g_cnt[i1], 1);
    }
}

__global__ void k_scan() {
    if (threadIdx.x == 0) {
        int acc = 0;
        for (int e = 0; e < NE; e++) {
            g_off[e] = acc; acc += g_cnt[e]; g_cur[e] = 0;
        }
        g_off[NE] = acc;
    }
}

__global__ void k_scatter() {
    int t = blockIdx.x * 256 + threadIdx.x;
    if (t >= NTOK) return;
#pragma unroll
    for (int k = 0; k < 2; k++) {
        int e = g_tidx[t * 2 + k];
        int p = atomicAdd(&g_cur[e], 1);
        int row = g_off[e] + p;
        g_tok[row] = t;
        g_trow[t * 2 + k] = row;
    }
}

/* g_hh = fp16( g_h2 * silu(g_h1) ) */
__global__ void k_silu() {
    size_t i = ((size_t)blockIdx.x * 256 + threadIdx.x) * 4;
    float4 a = *(float4*)&g_h1[i];
    float4 b = *(float4*)&g_h2[i];
    float h0 = b.x * a.x / (1.f + __expf(-a.x));
    float h1 = b.y * a.y / (1.f + __expf(-a.y));
    float h2 = b.z * a.z / (1.f + __expf(-a.z));
    float h3 = b.w * a.w / (1.f + __expf(-a.w));
    __half2* dst = (__half2*)&g_hh[i];
    dst[0] = __floats2half2_rn(h0, h1);
    dst[1] = __floats2half2_rn(h2, h3);
}

__global__ void k_combine(float* __restrict__ out) {
    int t = blockIdx.x;
    int   r0 = g_trow[t * 2],     r1 = g_trow[t * 2 + 1];
    float w0 = g_twgt[t * 2],     w1 = g_twgt[t * 2 + 1];
    const float* e0 = g_eo + (size_t)r0 * DM;
    const float* e1 = g_eo + (size_t)r1 * DM;
    float* op = out + (size_t)t * DM;
    for (int d = threadIdx.x; d < DM; d += 256)
        op[d] += w0 * e0[d] + w1 * e1[d];
}

/* --------------------------------- driver --------------------------------- */

extern "C" void kernel_launch(void* const* d_in, const int* in_sizes, int n_in,
                              void* d_out, int out_size) {
    const float* x   = (const float*)d_in[0];
    const float* n1w = (const float*)d_in[1];
    const float* Wq  = (const float*)d_in[2];
    const float* Wk  = (const float*)d_in[3];
    const float* Wv  = (const float*)d_in[4];
    const float* Wo  = (const float*)d_in[5];
    const float* n2w = (const float*)d_in[6];
    const float* rw  = (const float*)d_in[7];
    const float* rb  = (const float*)d_in[8];
    const float* W1  = (const float*)d_in[9];
    const float* b1  = (const float*)d_in[10];
    const float* W2  = (const float*)d_in[11];
    const float* b2  = (const float*)d_in[12];
    const float* W3  = (const float*)d_in[13];
    const float* b3  = (const float*)d_in[14];
    float* out = (float*)d_out;

    cudaFuncSetAttribute(k_tgemm, cudaFuncAttributeMaxDynamicSharedMemorySize,
                         TG_SMEM);
    cudaFuncSetAttribute(k_qkv, cudaFuncAttributeMaxDynamicSharedMemorySize,
                         TG_SMEM);

    void *p_wq, *p_wk, *p_wv, *p_wo, *p_w1, *p_w2, *p_w3;
    void *p_attnh, *p_hnrh, *p_hh, *p_h1, *p_h2, *p_eo, *p_off, *p_tok;
    cudaGetSymbolAddress(&p_wq, g_wq);
    cudaGetSymbolAddress(&p_wk, g_wk);
    cudaGetSymbolAddress(&p_wv, g_wv);
    cudaGetSymbolAddress(&p_wo, g_wo);
    cudaGetSymbolAddress(&p_w1, g_w1);
    cudaGetSymbolAddress(&p_w2, g_w2);
    cudaGetSymbolAddress(&p_w3, g_w3);
    cudaGetSymbolAddress(&p_attnh, g_attnh);
    cudaGetSymbolAddress(&p_hnrh,  g_hnrh);
    cudaGetSymbolAddress(&p_hh,    g_hh);
    cudaGetSymbolAddress(&p_h1,    g_h1);
    cudaGetSymbolAddress(&p_h2,    g_h2);
    cudaGetSymbolAddress(&p_eo,    g_eo);
    cudaGetSymbolAddress(&p_off,   g_off);
    cudaGetSymbolAddress(&p_tok,   g_tok);

    k_zero<<<1, 32>>>();

    /* weight conversions fp32 -> fp16 */
    {
        int n;
        n = DM*DM/4;        k_cvt<<<(n+255)/256,256>>>((const float4*)Wq, (__half2*)p_wq, n);
        n = DM*NG*DK/4;     k_cvt<<<(n+255)/256,256>>>((const float4*)Wk, (__half2*)p_wk, n);
        n = DM*NG*DK/4;     k_cvt<<<(n+255)/256,256>>>((const float4*)Wv, (__half2*)p_wv, n);
        n = DM*DM/4;        k_cvt<<<(n+255)/256,256>>>((const float4*)Wo, (__half2*)p_wo, n);
        n = NE*DM*DFF/4;    k_cvt<<<(n+255)/256,256>>>((const float4*)W1, (__half2*)p_w1, n);
        n = NE*DM*DFF/4;    k_cvt<<<(n+255)/256,256>>>((const float4*)W2, (__half2*)p_w2, n);
        n = NE*DFF*DM/4;    k_cvt<<<(n+255)/256,256>>>((const float4*)W3, (__half2*)p_w3, n);
    }

    k_norm_rope<<<NTOK, 256>>>(x, n1w);

    /* fused Q/K/V projections */
    k_qkv<<<dim3(12, NTOK/128, 1), 512, TG_SMEM>>>();

    /* split-K flash attention */
    k_attn_split<<<dim3(36, NH, BATCH), 128>>>();
    k_attn_combine<<<NROWS/256, 256>>>();

    /* out = x + attn @ Wo */
    k_tgemm<<<dim3(DM/128, NTOK/128, 1), 512, TG_SMEM>>>(
        (const __half*)p_attnh, DM, (const __half*)p_wo, 0, 0, 0, x,
        out, DM, NTOK, DM, DM, 0, 0);

    k_rmsnorm<<<NTOK, 256>>>(out, n2w);

    k_router<<<NTOK/8, 256>>>(rw, rb);
    k_scan<<<1, 32>>>();
    k_scatter<<<NTOK/256, 256>>>();

    /* expert FFN */
    k_tgemm<<<dim3(DFF/128, NTOK/128, NE), 512, TG_SMEM>>>(
        (const __half*)p_hnrh, DM, (const __half*)p_w1, (long)DM*DFF, b1, DFF, 0,
        (float*)p_h1, DFF, 0, DFF, DM, (const int*)p_off, (const int*)p_tok);
    k_tgemm<<<dim3(DFF/128, NTOK/128, NE), 512, TG_SMEM>>>(
        (const __half*)p_hnrh, DM, (const __half*)p_w2, (long)DM*DFF, b2, DFF, 0,
        (float*)p_h2, DFF, 0, DFF, DM, (const int*)p_off, (const int*)p_tok);
    k_silu<<<(NASSIGN*(DFF/4))/256, 256>>>();
    k_tgemm<<<dim3(DM/128, NTOK/128, NE), 512, TG_SMEM>>>(
        (const __half*)p_hh, DFF, (const __half*)p_w3, (long)DFF*DM, b3, DM, 0,
        (float*)p_eo, DM, 0, DM, DFF, (const int*)p_off, 0);

    k_combine<<<NTOK, 256>>>(out);
}